// round 17
// baseline (speedup 1.0000x reference)
#include <cuda_runtime.h>
#include <cooperative_groups.h>
namespace cg = cooperative_groups;

#define BB 32
#define CC 512
#define HC 128
#define HW 4096
#define NPLANE (BB * CC)
#define NBLK 512                     /* persistent grid: one plane-column per block */
#define EPS_BN 0.001f

// scratch (no device allocations allowed anywhere)
__device__ float g_s[BB * CC];      // pooled means [B, C]
__device__ float g_es[BB * CC];     // e * scale2   [B, C]
__device__ float g_shift[CC];       // shift2       [C]

// ---------------------------------------------------------------------------
// Single cooperative kernel: warp-per-plane reduce -> excite -> persistent
// scale, with exactly two grid syncs and zero kernel boundaries.
// ---------------------------------------------------------------------------
__global__ void __launch_bounds__(256) se_coop(
    const float* __restrict__ x, float* __restrict__ y,
    const float* __restrict__ w1, const float* __restrict__ g1,
    const float* __restrict__ b1, const float* __restrict__ m1,
    const float* __restrict__ v1, const float* __restrict__ w2,
    const float* __restrict__ g2, const float* __restrict__ b2,
    const float* __restrict__ m2, const float* __restrict__ v2) {

    cg::grid_group grid = cg::this_grid();
    const int tid  = threadIdx.x;
    const int wid  = tid >> 5;
    const int lane = tid & 31;

    // ================= pass R: warp-per-plane means (sync-free) =============
    // 512 blocks * 8 warps = 4096 warps; each warp reduces 4 planes alone.
    {
        const int W = blockIdx.x * 8 + wid;          // global warp id
#pragma unroll
        for (int j = 0; j < 4; j++) {
            const int plane = W + 4096 * j;
            const float4* xp = reinterpret_cast<const float4*>(x) +
                               (size_t)plane * (HW / 4) + lane;
            float sum = 0.f;
#pragma unroll 8
            for (int i = 0; i < 32; i++) {           // 32 coalesced 512B bursts
                float4 v = xp[i * 32];
                sum += (v.x + v.y) + (v.z + v.w);
            }
#pragma unroll
            for (int o = 16; o > 0; o >>= 1)
                sum += __shfl_down_sync(0xffffffffu, sum, o);
            if (lane == 0) g_s[plane] = sum * (1.0f / HW);
        }
    }
    grid.sync();

    // ================= excite: blocks 0..31 (one per batch) =================
    if (blockIdx.x < BB) {
        __shared__ float s_s[CC];
        __shared__ float s_h[HC];
        const int b = blockIdx.x;

        for (int i = tid; i < CC; i += 256) s_s[i] = g_s[b * CC + i];
        __syncthreads();

#pragma unroll 2
        for (int r = 0; r < 16; r++) {
            const int j = wid * 16 + r;
            const float* wr = w1 + j * CC;
            float acc = 0.f;
#pragma unroll
            for (int i = 0; i < CC / 32; i++)
                acc = fmaf(wr[lane + 32 * i], s_s[lane + 32 * i], acc);
#pragma unroll
            for (int o = 16; o > 0; o >>= 1)
                acc += __shfl_down_sync(0xffffffffu, acc, o);
            if (lane == 0) {
                float hv = (acc - m1[j]) * (g1[j] * rsqrtf(v1[j] + EPS_BN)) + b1[j];
                s_h[j] = fmaxf(hv, 0.f);
            }
        }
        __syncthreads();

#pragma unroll 2
        for (int r = 0; r < 64; r++) {
            const int c = wid * 64 + r;
            const float* wr = w2 + c * HC;
            float acc = 0.f;
#pragma unroll
            for (int i = 0; i < HC / 32; i++)
                acc = fmaf(wr[lane + 32 * i], s_h[lane + 32 * i], acc);
#pragma unroll
            for (int o = 16; o > 0; o >>= 1)
                acc += __shfl_down_sync(0xffffffffu, acc, o);
            if (lane == 0) {
                const float sc2 = g2[c] * rsqrtf(v2[c] + EPS_BN);
                g_es[b * CC + c] = acc * sc2;
                if (b == 0) g_shift[c] = fmaf(-m2[c], sc2, b2[c]);
            }
        }
    }
    grid.sync();

    // ================= pass S: persistent scale (R15 consumer shape) ========
    {
        const float shift = g_shift[blockIdx.x];     // plane % CC == blockIdx.x
        for (int k = 0; k < BB; k++) {
            const int plane = k * CC + blockIdx.x;
            const float es = __ldcg(&g_es[plane]);
            const size_t base = (size_t)plane * (HW / 4);
            const float4* xp = reinterpret_cast<const float4*>(x) + base + tid;
            float4*       yp = reinterpret_cast<float4*>(y) + base + tid;

            float4 v[4];
#pragma unroll
            for (int i = 0; i < 4; i++) v[i] = __ldcg(xp + i * 256);
#pragma unroll
            for (int i = 0; i < 4; i++) {
                float4 o;
                o.x = fmaf(v[i].x, es, shift);
                o.y = fmaf(v[i].y, es, shift);
                o.z = fmaf(v[i].z, es, shift);
                o.w = fmaf(v[i].w, es, shift);
                __stcs(yp + i * 256, o);
            }
        }
    }
}

// ---------------------------------------------------------------------------
// Fallback: proven R13 path (plain launches) if cooperative launch fails.
// ---------------------------------------------------------------------------
__global__ void __launch_bounds__(256) se_reduce(const float* __restrict__ x) {
    const int plane = blockIdx.x;
    const float4* xp = reinterpret_cast<const float4*>(x + (size_t)plane * HW)
                       + threadIdx.x;
    float sum = 0.f;
#pragma unroll
    for (int i = 0; i < 4; i++) {
        float4 v = xp[i * 256];
        sum += (v.x + v.y) + (v.z + v.w);
    }
#pragma unroll
    for (int o = 16; o > 0; o >>= 1) sum += __shfl_down_sync(0xffffffffu, sum, o);
    __shared__ float red[8];
    if ((threadIdx.x & 31) == 0) red[threadIdx.x >> 5] = sum;
    __syncthreads();
    if (threadIdx.x == 0) {
        float s = 0.f;
#pragma unroll
        for (int i = 0; i < 8; i++) s += red[i];
        g_s[plane] = s * (1.0f / HW);
    }
}

__global__ void __launch_bounds__(256) se_excite(
    const float* __restrict__ w1, const float* __restrict__ g1,
    const float* __restrict__ b1, const float* __restrict__ m1,
    const float* __restrict__ v1, const float* __restrict__ w2,
    const float* __restrict__ g2, const float* __restrict__ b2,
    const float* __restrict__ m2, const float* __restrict__ v2) {
    __shared__ float s_s[CC];
    __shared__ float s_h[HC];
    const int b = blockIdx.x, wid = threadIdx.x >> 5, lane = threadIdx.x & 31;
    for (int i = threadIdx.x; i < CC; i += 256) s_s[i] = g_s[b * CC + i];
    __syncthreads();
#pragma unroll 2
    for (int r = 0; r < 16; r++) {
        const int j = wid * 16 + r;
        const float* wr = w1 + j * CC;
        float acc = 0.f;
#pragma unroll
        for (int i = 0; i < CC / 32; i++)
            acc = fmaf(wr[lane + 32 * i], s_s[lane + 32 * i], acc);
#pragma unroll
        for (int o = 16; o > 0; o >>= 1) acc += __shfl_down_sync(0xffffffffu, acc, o);
        if (lane == 0) {
            float hv = (acc - m1[j]) * (g1[j] * rsqrtf(v1[j] + EPS_BN)) + b1[j];
            s_h[j] = fmaxf(hv, 0.f);
        }
    }
    __syncthreads();
#pragma unroll 2
    for (int r = 0; r < 64; r++) {
        const int c = wid * 64 + r;
        const float* wr = w2 + c * HC;
        float acc = 0.f;
#pragma unroll
        for (int i = 0; i < HC / 32; i++)
            acc = fmaf(wr[lane + 32 * i], s_h[lane + 32 * i], acc);
#pragma unroll
        for (int o = 16; o > 0; o >>= 1) acc += __shfl_down_sync(0xffffffffu, acc, o);
        if (lane == 0) {
            const float sc2 = g2[c] * rsqrtf(v2[c] + EPS_BN);
            g_es[b * CC + c] = acc * sc2;
            if (b == 0) g_shift[c] = fmaf(-m2[c], sc2, b2[c]);
        }
    }
}

__global__ void __launch_bounds__(256) se_scale(const float* __restrict__ x,
                                                float* __restrict__ y) {
    const int plane0 = NPLANE - 2 - blockIdx.x * 2;
    float es[2], sh[2];
#pragma unroll
    for (int p = 0; p < 2; p++) {
        es[p] = g_es[plane0 + p];
        sh[p] = g_shift[(plane0 + p) & (CC - 1)];
    }
    const size_t base = (size_t)plane0 * (HW / 4);
    const float4* xp = reinterpret_cast<const float4*>(x) + base + threadIdx.x;
    float4*       yp = reinterpret_cast<float4*>(y) + base + threadIdx.x;
    float4 v[8];
#pragma unroll
    for (int i = 0; i < 8; i++) v[i] = __ldcg(xp + i * 256);
#pragma unroll
    for (int i = 0; i < 8; i++) {
        const float e = es[i >> 2], s = sh[i >> 2];
        float4 o;
        o.x = fmaf(v[i].x, e, s); o.y = fmaf(v[i].y, e, s);
        o.z = fmaf(v[i].z, e, s); o.w = fmaf(v[i].w, e, s);
        __stcs(yp + i * 256, o);
    }
}

// ---------------------------------------------------------------------------
extern "C" void kernel_launch(void* const* d_in, const int* in_sizes, int n_in,
                              void* d_out, int out_size) {
    const float* x  = (const float*)d_in[0];
    const float* w1 = (const float*)d_in[1];
    const float* g1 = (const float*)d_in[2];
    const float* b1 = (const float*)d_in[3];
    const float* m1 = (const float*)d_in[4];
    const float* v1 = (const float*)d_in[5];
    const float* w2 = (const float*)d_in[6];
    const float* g2 = (const float*)d_in[7];
    const float* b2 = (const float*)d_in[8];
    const float* m2 = (const float*)d_in[9];
    const float* v2 = (const float*)d_in[10];
    float* y = (float*)d_out;

    // verify 512 blocks can be co-resident (once, on the uncaptured call)
    static int coopOK = -1;
    if (coopOK < 0) {
        int dev = 0, sms = 0, perSM = 0;
        cudaGetDevice(&dev);
        cudaDeviceGetAttribute(&sms, cudaDevAttrMultiProcessorCount, dev);
        cudaOccupancyMaxActiveBlocksPerMultiprocessor(&perSM, se_coop, 256, 0);
        coopOK = (sms * perSM >= NBLK) ? 1 : 0;
    }

    bool ok = false;
    if (coopOK == 1) {
        void* args[] = {(void*)&x, (void*)&y,
                        (void*)&w1, (void*)&g1, (void*)&b1, (void*)&m1, (void*)&v1,
                        (void*)&w2, (void*)&g2, (void*)&b2, (void*)&m2, (void*)&v2};
        cudaError_t err = cudaLaunchCooperativeKernel(
            (void*)se_coop, dim3(NBLK), dim3(256), args, 0, (cudaStream_t)0);
        ok = (err == cudaSuccess);
        if (!ok) (void)cudaGetLastError();
    }

    if (!ok) {   // proven fallback (R13 kernels, plain launches)
        se_reduce<<<NPLANE, 256>>>(x);
        se_excite<<<BB, 256>>>(w1, g1, b1, m1, v1, w2, g2, b2, m2, v2);
        se_scale<<<NPLANE / 2, 256>>>(x, y);
    }
}